// round 2
// baseline (speedup 1.0000x reference)
#include <cuda_runtime.h>

#define NB 256
#define NP 20000

// scratch: 256 batches x 45 packed upper-triangular entries of XwX
__device__ float g_M[NB * 45];

__device__ __host__ __forceinline__ constexpr int tidx(int i, int j) {
    return 9 * i - i * (i - 1) / 2 + (j - i);
}

// ---------------------------------------------------------------------------
// Kernel 1: per-batch weighted Gram matrix (HBM-bound, ~100MB read once)
// ---------------------------------------------------------------------------
__global__ void __launch_bounds__(256) xtx_kernel(const float4* __restrict__ x,
                                                  const float* __restrict__ w) {
    int b = blockIdx.x;
    const float4* xb = x + (size_t)b * NP;
    const float*  wb = w + (size_t)b * NP;

    float s[45];
#pragma unroll
    for (int k = 0; k < 45; k++) s[k] = 0.f;

    for (int i = threadIdx.x; i < NP; i += 256) {
        float4 p = xb[i];
        float wt = wb[i];
        float v[9];
        v[0] = p.z * p.x; v[1] = p.z * p.y; v[2] = p.z;
        v[3] = p.w * p.x; v[4] = p.w * p.y; v[5] = p.w;
        v[6] = p.x;       v[7] = p.y;       v[8] = 1.f;
        float wv[9];
#pragma unroll
        for (int k = 0; k < 9; k++) wv[k] = wt * v[k];
        int idx = 0;
#pragma unroll
        for (int i2 = 0; i2 < 9; i2++) {
#pragma unroll
            for (int j = i2; j < 9; j++) {
                s[idx] = fmaf(v[i2], wv[j], s[idx]);
                idx++;
            }
        }
    }

#pragma unroll
    for (int k = 0; k < 45; k++) {
#pragma unroll
        for (int o = 16; o > 0; o >>= 1)
            s[k] += __shfl_xor_sync(0xffffffffu, s[k], o);
    }

    __shared__ float sm[8][45];
    int wid = threadIdx.x >> 5, lane = threadIdx.x & 31;
    if (lane == 0) {
#pragma unroll
        for (int k = 0; k < 45; k++) sm[wid][k] = s[k];
    }
    __syncthreads();
    if (threadIdx.x < 45) {
        float t = 0.f;
#pragma unroll
        for (int q = 0; q < 8; q++) t += sm[q][threadIdx.x];
        g_M[b * 45 + threadIdx.x] = t;
    }
}

// ---------------------------------------------------------------------------
// LAPACK ssyevd replica helpers (fp32, reference netlib semantics)
// ---------------------------------------------------------------------------
#define LEPS    5.9604645e-8f       /* slamch('E') for fp32 */
#define LEPS2   (LEPS * LEPS)
#define LSAFMIN 1.17549435e-38f

__device__ __forceinline__ float slapy2(float x, float y) {
    float xa = fabsf(x), ya = fabsf(y);
    float w = fmaxf(xa, ya), z = fminf(xa, ya);
    if (z == 0.f) return w;
    float t = z / w;
    return w * sqrtf(1.f + t * t);
}

// LAPACK >= 3.10 slartg (real): c >= 0, r = sign(f)*hypot
__device__ __forceinline__ void slartg(float f, float g, float& c, float& s, float& r) {
    if (g == 0.f) { c = 1.f; s = 0.f; r = f; }
    else if (f == 0.f) { c = 0.f; s = (g >= 0.f ? 1.f : -1.f); r = fabsf(g); }
    else {
        float d = sqrtf(f * f + g * g);
        c = fabsf(f) / d;
        r = copysignf(d, f);
        s = g / r;
    }
}

__device__ void slaev2(float a, float b, float c,
                       float& rt1, float& rt2, float& cs1, float& sn1) {
    float sm = a + c, df = a - c, adf = fabsf(df);
    float tb = b + b, ab = fabsf(tb);
    float acmx, acmn;
    if (fabsf(a) > fabsf(c)) { acmx = a; acmn = c; } else { acmx = c; acmn = a; }
    float rt;
    if (adf > ab)      { float t = ab / adf; rt = adf * sqrtf(1.f + t * t); }
    else if (adf < ab) { float t = adf / ab; rt = ab * sqrtf(1.f + t * t); }
    else               { rt = ab * sqrtf(2.f); }
    int sgn1;
    if (sm < 0.f) {
        rt1 = 0.5f * (sm - rt); sgn1 = -1;
        rt2 = (acmx / rt1) * acmn - (b / rt1) * b;
    } else if (sm > 0.f) {
        rt1 = 0.5f * (sm + rt); sgn1 = 1;
        rt2 = (acmx / rt1) * acmn - (b / rt1) * b;
    } else {
        rt1 = 0.5f * rt; rt2 = -0.5f * rt; sgn1 = 1;
    }
    float cs; int sgn2;
    if (df >= 0.f) { cs = df + rt; sgn2 = 1; } else { cs = df - rt; sgn2 = -1; }
    float acs = fabsf(cs);
    if (acs > ab) {
        float ct = -tb / cs;
        sn1 = 1.f / sqrtf(1.f + ct * ct);
        cs1 = ct * sn1;
    } else {
        if (ab == 0.f) { cs1 = 1.f; sn1 = 0.f; }
        else {
            float tn = -cs / tb;
            cs1 = 1.f / sqrtf(1.f + tn * tn);
            sn1 = tn * cs1;
        }
    }
    if (sgn1 == sgn2) { float tn = cs1; cs1 = -sn1; sn1 = tn; }
}

// ---------------------------------------------------------------------------
// Kernel 2: per-matrix LAPACK ssyevd replica (ssytd2 + ssteqr + backtransform)
// one matrix per thread, one thread per block (divergence-free, latency-bound)
// ---------------------------------------------------------------------------
__global__ void eig_kernel(float* __restrict__ out) {
    int b = blockIdx.x;

    float A[9][9];
#pragma unroll
    for (int i = 0; i < 9; i++)
#pragma unroll
        for (int j = i; j < 9; j++) {
            float v = g_M[b * 45 + tidx(i, j)];
            A[i][j] = v; A[j][i] = v;
        }

    float dd[9], e[8], tau[8];

    // ---- ssytd2 (lower) ----
    for (int i = 0; i < 8; i++) {
        float alpha = A[i + 1][i];
        float xn2 = 0.f;
        for (int k = i + 2; k < 9; k++) xn2 += A[k][i] * A[k][i];
        float taui;
        if (xn2 == 0.f) {
            taui = 0.f;
            e[i] = alpha;
        } else {
            float xnorm = sqrtf(xn2);
            float beta = -copysignf(slapy2(alpha, xnorm), alpha);
            taui = (beta - alpha) / beta;
            float invd = 1.f / (alpha - beta);
            for (int k = i + 2; k < 9; k++) A[k][i] *= invd;
            e[i] = beta;
        }
        if (taui != 0.f) {
            float v[9], wv[9];
            v[i + 1] = 1.f;
            for (int k = i + 2; k < 9; k++) v[k] = A[k][i];
            for (int r = i + 1; r < 9; r++) {
                float acc = 0.f;
                for (int c = i + 1; c < 9; c++) acc += A[r][c] * v[c];
                wv[r] = taui * acc;
            }
            float dxv = 0.f;
            for (int r = i + 1; r < 9; r++) dxv += wv[r] * v[r];
            float al2 = -0.5f * taui * dxv;
            for (int r = i + 1; r < 9; r++) wv[r] += al2 * v[r];
            for (int r = i + 1; r < 9; r++)
                for (int c = i + 1; c < 9; c++)
                    A[r][c] -= v[r] * wv[c] + wv[r] * v[c];
        }
        dd[i] = A[i][i];
        tau[i] = taui;
    }
    dd[8] = A[8][8];

    // ---- ssteqr (compz='I') ----
    float Z[9][9];
    for (int r = 0; r < 9; r++)
        for (int c = 0; c < 9; c++) Z[r][c] = (r == c) ? 1.f : 0.f;

    const int NMAXIT = 9 * 30;
    int jtot = 0;
    int l1 = 0;
    while (l1 < 9) {
        if (l1 > 0) e[l1 - 1] = 0.f;
        int m;
        for (m = l1; m < 8; m++) {
            float tst = fabsf(e[m]);
            if (tst == 0.f) break;
            if (tst <= (sqrtf(fabsf(dd[m])) * sqrtf(fabsf(dd[m + 1]))) * LEPS) {
                e[m] = 0.f;
                break;
            }
        }
        int l = l1, lend = m;
        l1 = m + 1;
        if (lend == l) continue;
        if (fabsf(dd[lend]) < fabsf(dd[l])) { int t = l; l = lend; lend = t; }

        if (lend > l) {
            // ---- QL iteration ----
            for (;;) {
                int mm;
                for (mm = l; mm < lend; mm++) {
                    float tst = e[mm] * e[mm];
                    if (tst <= (LEPS2 * fabsf(dd[mm])) * fabsf(dd[mm + 1]) + LSAFMIN) break;
                }
                if (mm < lend) e[mm] = 0.f;
                float p = dd[l];
                if (mm == l) {                       // eigenvalue found
                    dd[l] = p;
                    l++;
                    if (l <= lend) continue;
                    break;
                }
                if (mm == l + 1) {                   // 2x2 block
                    float rt1, rt2, c2, s2;
                    slaev2(dd[l], e[l], dd[l + 1], rt1, rt2, c2, s2);
                    for (int r = 0; r < 9; r++) {
                        float t2 = Z[r][l + 1];
                        Z[r][l + 1] = c2 * t2 - s2 * Z[r][l];
                        Z[r][l]     = s2 * t2 + c2 * Z[r][l];
                    }
                    dd[l] = rt1; dd[l + 1] = rt2; e[l] = 0.f;
                    l += 2;
                    if (l <= lend) continue;
                    break;
                }
                if (jtot >= NMAXIT) break;
                jtot++;
                float g = (dd[l + 1] - p) / (2.f * e[l]);
                float r2 = slapy2(g, 1.f);
                g = dd[mm] - p + e[l] / (g + copysignf(r2, g));
                float s1 = 1.f, c1 = 1.f;
                p = 0.f;
                float cs_[8], sn_[8];
                for (int i = mm - 1; i >= l; i--) {
                    float f = s1 * e[i];
                    float bb = c1 * e[i];
                    slartg(g, f, c1, s1, r2);
                    if (i != mm - 1) e[i + 1] = r2;
                    g = dd[i + 1] - p;
                    r2 = (dd[i] - g) * s1 + 2.f * c1 * bb;
                    p = s1 * r2;
                    dd[i + 1] = g + p;
                    g = c1 * r2 - bb;
                    cs_[i] = c1; sn_[i] = -s1;
                }
                for (int j = mm - 1 - l; j >= 0; j--) {   // slasr 'R','V','B'
                    float cc = cs_[l + j], ss = sn_[l + j];
                    for (int r = 0; r < 9; r++) {
                        float t2 = Z[r][l + j + 1];
                        Z[r][l + j + 1] = cc * t2 - ss * Z[r][l + j];
                        Z[r][l + j]     = ss * t2 + cc * Z[r][l + j];
                    }
                }
                dd[l] = dd[l] - p;
                e[l] = g;
            }
        } else {
            // ---- QR iteration (lend < l) ----
            for (;;) {
                int mm;
                for (mm = l; mm > lend; mm--) {
                    float tst = e[mm - 1] * e[mm - 1];
                    if (tst <= (LEPS2 * fabsf(dd[mm])) * fabsf(dd[mm - 1]) + LSAFMIN) break;
                }
                if (mm > lend) e[mm - 1] = 0.f;
                float p = dd[l];
                if (mm == l) {
                    dd[l] = p;
                    l--;
                    if (l >= lend) continue;
                    break;
                }
                if (mm == l - 1) {
                    float rt1, rt2, c2, s2;
                    slaev2(dd[l - 1], e[l - 1], dd[l], rt1, rt2, c2, s2);
                    for (int r = 0; r < 9; r++) {   // slasr 'F', 2 cols at l-1
                        float t2 = Z[r][l];
                        Z[r][l]     = c2 * t2 - s2 * Z[r][l - 1];
                        Z[r][l - 1] = s2 * t2 + c2 * Z[r][l - 1];
                    }
                    dd[l - 1] = rt1; dd[l] = rt2; e[l - 1] = 0.f;
                    l -= 2;
                    if (l >= lend) continue;
                    break;
                }
                if (jtot >= NMAXIT) break;
                jtot++;
                float g = (dd[l - 1] - p) / (2.f * e[l - 1]);
                float r2 = slapy2(g, 1.f);
                g = dd[mm] - p + e[l - 1] / (g + copysignf(r2, g));
                float s1 = 1.f, c1 = 1.f;
                p = 0.f;
                float cs_[8], sn_[8];
                for (int i = mm; i <= l - 1; i++) {
                    float f = s1 * e[i];
                    float bb = c1 * e[i];
                    slartg(g, f, c1, s1, r2);
                    if (i != mm) e[i - 1] = r2;
                    g = dd[i] - p;
                    r2 = (dd[i + 1] - g) * s1 + 2.f * c1 * bb;
                    p = s1 * r2;
                    dd[i] = g + p;
                    g = c1 * r2 - bb;
                    cs_[i] = c1; sn_[i] = s1;
                }
                for (int j = 0; j <= l - mm - 1; j++) {   // slasr 'R','V','F'
                    float cc = cs_[mm + j], ss = sn_[mm + j];
                    for (int r = 0; r < 9; r++) {
                        float t2 = Z[r][mm + j + 1];
                        Z[r][mm + j + 1] = cc * t2 - ss * Z[r][mm + j];
                        Z[r][mm + j]     = ss * t2 + cc * Z[r][mm + j];
                    }
                }
                dd[l] = dd[l] - p;
                e[l - 1] = g;
            }
        }
    }

    // ---- ssteqr final sort: ascending eigenvalues, swap columns ----
    for (int ii = 1; ii < 9; ii++) {
        int i = ii - 1;
        int k = i;
        float p = dd[i];
        for (int j = ii; j < 9; j++)
            if (dd[j] < p) { k = j; p = dd[j]; }
        if (k != i) {
            dd[k] = dd[i]; dd[i] = p;
            for (int r = 0; r < 9; r++) {
                float t2 = Z[r][i]; Z[r][i] = Z[r][k]; Z[r][k] = t2;
            }
        }
    }

    // ---- back-transform column 0: z <- H(1)...H(8) z ----
    float z[9];
    for (int r = 0; r < 9; r++) z[r] = Z[r][0];
    for (int i = 7; i >= 0; i--) {
        if (tau[i] == 0.f) continue;
        float dot = z[i + 1];
        for (int k = i + 2; k < 9; k++) dot += A[k][i] * z[k];
        float tdot = tau[i] * dot;
        z[i + 1] -= tdot;
        for (int k = i + 2; k < 9; k++) z[k] -= tdot * A[k][i];
    }

    // ---- normalize (reference divides by norm) ----
    float nrm = 0.f;
    for (int k = 0; k < 9; k++) nrm += z[k] * z[k];
    float inv = 1.f / sqrtf(nrm);
    for (int k = 0; k < 9; k++) out[b * 9 + k] = z[k] * inv;
}

extern "C" void kernel_launch(void* const* d_in, const int* in_sizes, int n_in,
                              void* d_out, int out_size) {
    const float4* x = (const float4*)d_in[0];  // x_in  (256,1,20000,4) f32
    const float*  w = (const float*)d_in[1];   // weights (256,20000)   f32
    float* out = (float*)d_out;                // (256,9) f32

    xtx_kernel<<<NB, 256>>>(x, w);
    eig_kernel<<<NB, 1>>>(out);
}